// round 1
// baseline (speedup 1.0000x reference)
#include <cuda_runtime.h>

// LSTMBrain: 2-layer LSTM (hidden=3) over [B=4096, T=2048] scalar sequences,
// then dense head 3->1. Output [1, B] float32.
//
// Inputs (metadata order):
//  0: state [B, T] f32
//  1: W1 [1, 12]   2: U1 [3, 12]   3: b1 [12]
//  4: W2 [3, 12]   5: U2 [3, 12]   6: b2 [12]
//  7: Wd [3, 1]    8: bd [1]
//
// Round 1 design: one thread per batch element, weights in registers,
// accurate exp-based sigmoid/tanh (abs err ~1e-7 so recurrent accumulation
// over 2048 steps stays far under the 1e-3 threshold).

#define HID 3
#define G4 (4 * HID)

__device__ __forceinline__ float fast_rcp(float x) {
    float r;
    asm("rcp.approx.f32 %0, %1;" : "=f"(r) : "f"(x));
    return r;
}
__device__ __forceinline__ float fast_ex2(float x) {
    float r;
    asm("ex2.approx.f32 %0, %1;" : "=f"(r) : "f"(x));
    return r;
}
// sigmoid(x) = 1 / (1 + 2^(-x*log2(e)))
__device__ __forceinline__ float sigf(float x) {
    return fast_rcp(1.0f + fast_ex2(-1.4426950408889634f * x));
}
// tanh(x) = 2 / (1 + 2^(-2x*log2(e))) - 1
__device__ __forceinline__ float tanhf_fast(float x) {
    return fmaf(2.0f, fast_rcp(1.0f + fast_ex2(-2.8853900817779268f * x)), -1.0f);
}

__global__ void __launch_bounds__(32, 1) lstm2_kernel(
    const float* __restrict__ state,
    const float* __restrict__ W1, const float* __restrict__ U1, const float* __restrict__ b1,
    const float* __restrict__ W2, const float* __restrict__ U2, const float* __restrict__ b2,
    const float* __restrict__ Wd, const float* __restrict__ bd,
    float* __restrict__ out, int B, int T)
{
    const int b = blockIdx.x * 32 + threadIdx.x;
    if (b >= B) return;

    // ---- hoist all weights into registers (uniform across threads) ----
    float w1[G4], bb1[G4], bb2[G4];
    float u1[HID][G4], w2[HID][G4], u2[HID][G4];
#pragma unroll
    for (int j = 0; j < G4; ++j) {
        w1[j]  = __ldg(W1 + j);
        bb1[j] = __ldg(b1 + j);
        bb2[j] = __ldg(b2 + j);
    }
#pragma unroll
    for (int k = 0; k < HID; ++k) {
#pragma unroll
        for (int j = 0; j < G4; ++j) {
            u1[k][j] = __ldg(U1 + k * G4 + j);
            w2[k][j] = __ldg(W2 + k * G4 + j);
            u2[k][j] = __ldg(U2 + k * G4 + j);
        }
    }

    float h1[HID] = {0.f, 0.f, 0.f}, c1[HID] = {0.f, 0.f, 0.f};
    float h2[HID] = {0.f, 0.f, 0.f}, c2[HID] = {0.f, 0.f, 0.f};

    const float* xrow = state + (long long)b * (long long)T;

#define LSTM_STEP(xval)                                                          \
    do {                                                                         \
        const float x_ = (xval);                                                 \
        float z[G4];                                                             \
        /* layer 1: z = x*W1 + h1*U1 + b1 */                                     \
        _Pragma("unroll")                                                        \
        for (int j = 0; j < G4; ++j) {                                           \
            float v = fmaf(x_, w1[j], bb1[j]);                                   \
            v = fmaf(h1[0], u1[0][j], v);                                        \
            v = fmaf(h1[1], u1[1][j], v);                                        \
            v = fmaf(h1[2], u1[2][j], v);                                        \
            z[j] = v;                                                            \
        }                                                                        \
        float s1[HID];                                                           \
        _Pragma("unroll")                                                        \
        for (int u = 0; u < HID; ++u) {                                          \
            const float ig = sigf(z[u]);                                         \
            const float fg = sigf(z[HID + u]);                                   \
            const float gg = tanhf_fast(z[2 * HID + u]);                         \
            const float og = sigf(z[3 * HID + u]);                               \
            const float c  = fmaf(fg, c1[u], ig * gg);                           \
            c1[u] = c;                                                           \
            s1[u] = og * tanhf_fast(c);                                          \
        }                                                                        \
        /* layer 2: z = s1*W2 + h2*U2 + b2 */                                    \
        _Pragma("unroll")                                                        \
        for (int j = 0; j < G4; ++j) {                                           \
            float v = bb2[j];                                                    \
            v = fmaf(s1[0], w2[0][j], v);                                        \
            v = fmaf(s1[1], w2[1][j], v);                                        \
            v = fmaf(s1[2], w2[2][j], v);                                        \
            v = fmaf(h2[0], u2[0][j], v);                                        \
            v = fmaf(h2[1], u2[1][j], v);                                        \
            v = fmaf(h2[2], u2[2][j], v);                                        \
            z[j] = v;                                                            \
        }                                                                        \
        _Pragma("unroll")                                                        \
        for (int u = 0; u < HID; ++u) {                                          \
            const float ig = sigf(z[u]);                                         \
            const float fg = sigf(z[HID + u]);                                   \
            const float gg = tanhf_fast(z[2 * HID + u]);                         \
            const float og = sigf(z[3 * HID + u]);                               \
            const float c  = fmaf(fg, c2[u], ig * gg);                           \
            c2[u] = c;                                                           \
            h2[u] = og * tanhf_fast(c);                                          \
        }                                                                        \
        h1[0] = s1[0]; h1[1] = s1[1]; h1[2] = s1[2];                             \
    } while (0)

    int t = 0;
    // rows are 8KB and float4-aligned (T=2048); vector-load 4 steps at a time
    for (; t + 4 <= T; t += 4) {
        const float4 x4 = __ldg(reinterpret_cast<const float4*>(xrow + t));
        LSTM_STEP(x4.x);
        LSTM_STEP(x4.y);
        LSTM_STEP(x4.z);
        LSTM_STEP(x4.w);
    }
    for (; t < T; ++t) {
        LSTM_STEP(__ldg(xrow + t));
    }
#undef LSTM_STEP

    // dense head: out[b] = h2 . Wd + bd
    float r = __ldg(bd);
    r = fmaf(h2[0], __ldg(Wd + 0), r);
    r = fmaf(h2[1], __ldg(Wd + 1), r);
    r = fmaf(h2[2], __ldg(Wd + 2), r);
    out[b] = r;
}

extern "C" void kernel_launch(void* const* d_in, const int* in_sizes, int n_in,
                              void* d_out, int out_size)
{
    const float* state = (const float*)d_in[0];
    const float* W1 = (const float*)d_in[1];
    const float* U1 = (const float*)d_in[2];
    const float* b1 = (const float*)d_in[3];
    const float* W2 = (const float*)d_in[4];
    const float* U2 = (const float*)d_in[5];
    const float* b2 = (const float*)d_in[6];
    const float* Wd = (const float*)d_in[7];
    const float* bd = (const float*)d_in[8];
    float* out = (float*)d_out;

    const int B = out_size;               // output is [1, B]
    const int T = in_sizes[0] / B;        // state is [B, T]

    const int threads = 32;
    const int blocks = (B + threads - 1) / threads;
    lstm2_kernel<<<blocks, threads>>>(state, W1, U1, b1, W2, U2, b2, Wd, bd, out, B, T);
}

// round 2
// speedup vs baseline: 2.1355x; 2.1355x over previous
#include <cuda_runtime.h>

// LSTMBrain: 2-layer LSTM (hidden=3) over [B=4096, T=2048], dense head 3->1.
// Round 2: 4 lanes per batch element (lane u computes hidden unit u of BOTH
// layers; lane 3 duplicates unit 2 to avoid divergence). 512 warps instead of
// 128 -> ~4x scheduler coverage. Layers software-pipelined (L2(t-1) runs
// concurrently with L1(t)) for ILP. h1/h2 broadcast via width-4 shfl.

#define HID 3
#define FULLM 0xFFFFFFFFu

__device__ __forceinline__ float fast_rcp(float x) {
    float r; asm("rcp.approx.f32 %0, %1;" : "=f"(r) : "f"(x)); return r;
}
__device__ __forceinline__ float fast_ex2(float x) {
    float r; asm("ex2.approx.f32 %0, %1;" : "=f"(r) : "f"(x)); return r;
}
// sigmoid(x) = 1 / (1 + 2^(-x*log2e))   (abs err ~1e-7)
__device__ __forceinline__ float sigf(float x) {
    return fast_rcp(1.0f + fast_ex2(-1.4426950408889634f * x));
}
// tanh(x) = 2 / (1 + 2^(-2x*log2e)) - 1
__device__ __forceinline__ float tanhf_fast(float x) {
    return fmaf(2.0f, fast_rcp(1.0f + fast_ex2(-2.8853900817779268f * x)), -1.0f);
}

__global__ void __launch_bounds__(128, 1) lstm2_split_kernel(
    const float* __restrict__ state,
    const float* __restrict__ W1, const float* __restrict__ U1, const float* __restrict__ b1,
    const float* __restrict__ W2, const float* __restrict__ U2, const float* __restrict__ b2,
    const float* __restrict__ Wd, const float* __restrict__ bd,
    float* __restrict__ out, int B, int T)
{
    const int tid  = blockIdx.x * 128 + threadIdx.x;
    const int l    = tid & 3;              // sub-lane within 4-lane group
    const int u    = (l < 3) ? l : 2;      // hidden unit owned (lane 3 dups unit 2)
    int b = tid >> 2;                      // batch element for this group
    const bool writer = (l == 0) && (b < B);
    if (b >= B) b = B - 1;                 // clamp (keeps shfl convergent)

    // ---- per-lane weights: the 4 gate columns of unit u ----
    // z layout: [i0 i1 i2 | f0 f1 f2 | g0 g1 g2 | o0 o1 o2]; col(g) = g*3 + u
    float w1g[4], b1g[4], b2g[4];
    float u1g[HID][4], w2g[HID][4], u2g[HID][4];
#pragma unroll
    for (int g = 0; g < 4; ++g) {
        const int col = g * HID + u;
        w1g[g] = __ldg(W1 + col);
        b1g[g] = __ldg(b1 + col);
        b2g[g] = __ldg(b2 + col);
#pragma unroll
        for (int k = 0; k < HID; ++k) {
            u1g[k][g] = __ldg(U1 + k * 4 * HID + col);
            w2g[k][g] = __ldg(W2 + k * 4 * HID + col);
            u2g[k][g] = __ldg(U2 + k * 4 * HID + col);
        }
    }

    const float* xrow = state + (size_t)b * (size_t)T;

    float c1 = 0.f, c2 = 0.f;          // own-unit cell states
    float s1o = 0.f, h2o = 0.f;        // own-unit hidden outputs
    // broadcast states: S* = s1(t-1) (== h1 entering L1(t), and input to L2(t-1))
    //                   H* = h2(t-2) (hidden entering L2(t-1))
    float S0 = 0.f, S1 = 0.f, S2 = 0.f;
    float H0 = 0.f, H1 = 0.f, H2 = 0.f;

    // ---- layer-1 step: consumes x_t and S* (h1 state); produces s1o, updates c1
#define L1_STEP(xv)                                                        \
    do {                                                                   \
        float z[4];                                                       \
        _Pragma("unroll")                                                  \
        for (int g = 0; g < 4; ++g) {                                      \
            float v = fmaf((xv), w1g[g], b1g[g]);                          \
            v = fmaf(S0, u1g[0][g], v);                                    \
            v = fmaf(S1, u1g[1][g], v);                                    \
            v = fmaf(S2, u1g[2][g], v);                                    \
            z[g] = v;                                                      \
        }                                                                  \
        const float ig = sigf(z[0]);                                       \
        const float fg = sigf(z[1]);                                       \
        const float gg = tanhf_fast(z[2]);                                 \
        const float og = sigf(z[3]);                                       \
        c1 = fmaf(fg, c1, ig * gg);                                        \
        s1o = og * tanhf_fast(c1);                                         \
    } while (0)

    // ---- layer-2 step: consumes S* (s1 of its timestep) and H*; produces h2o
#define L2_STEP()                                                          \
    do {                                                                   \
        float z[4];                                                       \
        _Pragma("unroll")                                                  \
        for (int g = 0; g < 4; ++g) {                                      \
            float v = fmaf(S0, w2g[0][g], b2g[g]);                         \
            v = fmaf(S1, w2g[1][g], v);                                    \
            v = fmaf(S2, w2g[2][g], v);                                    \
            v = fmaf(H0, u2g[0][g], v);                                    \
            v = fmaf(H1, u2g[1][g], v);                                    \
            v = fmaf(H2, u2g[2][g], v);                                    \
            z[g] = v;                                                      \
        }                                                                  \
        const float ig = sigf(z[0]);                                       \
        const float fg = sigf(z[1]);                                       \
        const float gg = tanhf_fast(z[2]);                                 \
        const float og = sigf(z[3]);                                       \
        c2 = fmaf(fg, c2, ig * gg);                                        \
        h2o = og * tanhf_fast(c2);                                         \
    } while (0)

#define BCAST()                                                            \
    do {                                                                   \
        S0 = __shfl_sync(FULLM, s1o, 0, 4);                                \
        S1 = __shfl_sync(FULLM, s1o, 1, 4);                                \
        S2 = __shfl_sync(FULLM, s1o, 2, 4);                                \
        H0 = __shfl_sync(FULLM, h2o, 0, 4);                                \
        H1 = __shfl_sync(FULLM, h2o, 1, 4);                                \
        H2 = __shfl_sync(FULLM, h2o, 2, 4);                                \
    } while (0)

    // pipelined body: L2 for step (t-1) and L1 for step t are independent
#define BODY(xv)                                                           \
    do {                                                                   \
        L2_STEP();                                                         \
        L1_STEP(xv);                                                       \
        BCAST();                                                           \
    } while (0)

    // ---- prologue: L1(0) with zero state, then first broadcast (h2o = 0)
    L1_STEP(__ldg(xrow + 0));
    BCAST();

    // ---- main pipelined loop: t = 1 .. T-1
    int t = 1;
    for (; t + 4 <= T; t += 4) {
        const float x0 = __ldg(xrow + t + 0);
        const float x1 = __ldg(xrow + t + 1);
        const float x2 = __ldg(xrow + t + 2);
        const float x3 = __ldg(xrow + t + 3);
        BODY(x0);
        BODY(x1);
        BODY(x2);
        BODY(x3);
    }
    for (; t < T; ++t) {
        BODY(__ldg(xrow + t));
    }

    // ---- epilogue: final L2 (consumes s1(T-1) and h2(T-2) broadcasts)
    L2_STEP();
    // gather final h2 within the group
    const float F0 = __shfl_sync(FULLM, h2o, 0, 4);
    const float F1 = __shfl_sync(FULLM, h2o, 1, 4);
    const float F2 = __shfl_sync(FULLM, h2o, 2, 4);

    if (writer) {
        float r = __ldg(bd);
        r = fmaf(F0, __ldg(Wd + 0), r);
        r = fmaf(F1, __ldg(Wd + 1), r);
        r = fmaf(F2, __ldg(Wd + 2), r);
        out[b] = r;
    }

#undef L1_STEP
#undef L2_STEP
#undef BCAST
#undef BODY
}

extern "C" void kernel_launch(void* const* d_in, const int* in_sizes, int n_in,
                              void* d_out, int out_size)
{
    const float* state = (const float*)d_in[0];
    const float* W1 = (const float*)d_in[1];
    const float* U1 = (const float*)d_in[2];
    const float* b1 = (const float*)d_in[3];
    const float* W2 = (const float*)d_in[4];
    const float* U2 = (const float*)d_in[5];
    const float* b2 = (const float*)d_in[6];
    const float* Wd = (const float*)d_in[7];
    const float* bd = (const float*)d_in[8];
    float* out = (float*)d_out;

    const int B = out_size;            // output is [1, B]
    const int T = in_sizes[0] / B;     // state is [B, T]

    const int total_threads = B * 4;   // 4 lanes per element
    const int threads = 128;
    const int blocks = (total_threads + threads - 1) / threads;
    lstm2_split_kernel<<<blocks, threads>>>(state, W1, U1, b1, W2, U2, b2, Wd, bd, out, B, T);
}

// round 3
// speedup vs baseline: 2.1616x; 1.0122x over previous
#include <cuda_runtime.h>

// LSTMBrain: 2-layer LSTM (hidden=3) over [B=4096, T=2048], dense head 3->1.
// Round 3: 8 lanes per batch element.
//   lane 0..2 : layer-1 unit 0..2      lane 3 : dup of lane 2 (keeps shfl convergent)
//   lane 4..6 : layer-2 unit 0..2      lane 7 : dup of lane 6
// Unified cell form z_g = A_g*x + sum_k B_kg*S_k + sum_k C_kg*H_k + bias_g with
// per-lane coefficients (L1: C=0; L2: A=0), so all lanes execute ONE stream.
// Layers software-pipelined: at loop step t, L1 lanes compute s1(t), L2 lanes
// compute h2(t-1). S broadcasts s1, H broadcasts h2 (width-8 shfl).
// 1024 warps in 128 x 256-thread blocks -> uniform 2 warps/SMSP (MUFU overlap).
// Activation scale constants are pre-folded into the weight registers.

#define FULLM 0xFFFFFFFFu
#define LOG2E 1.4426950408889634f

__device__ __forceinline__ float fast_rcp(float x) {
    float r; asm("rcp.approx.f32 %0, %1;" : "=f"(r) : "f"(x)); return r;
}
__device__ __forceinline__ float fast_ex2(float x) {
    float r; asm("ex2.approx.f32 %0, %1;" : "=f"(r) : "f"(x)); return r;
}

__global__ void __launch_bounds__(256, 1) lstm2_8lane_kernel(
    const float* __restrict__ state,
    const float* __restrict__ W1, const float* __restrict__ U1, const float* __restrict__ b1,
    const float* __restrict__ W2, const float* __restrict__ U2, const float* __restrict__ b2,
    const float* __restrict__ Wd, const float* __restrict__ bd,
    float* __restrict__ out, int B, int T)
{
    const int tid   = blockIdx.x * 256 + threadIdx.x;
    const int lane8 = tid & 7;                 // position within 8-lane group
    const int sub   = lane8 & 3;
    const int u     = (sub < 3) ? sub : 2;     // hidden unit owned (lane 3/7 dup)
    const bool isL2 = (lane8 & 4) != 0;        // lanes 4..7 handle layer 2
    int b = tid >> 3;                          // batch element of this group
    const bool writer = (lane8 == 0) && (b < B);
    if (b >= B) b = B - 1;                     // clamp (keeps shfls convergent)

    // ---- per-lane coefficients, pre-scaled into the ex2 domain ----
    // gate order g = 0:i(sigma) 1:f(sigma) 2:g(tanh) 3:o(sigma); column = g*3+u
    // sigma(y) = rcp(1 + ex2(-log2e * y)); tanh(y) = 2*rcp(1 + ex2(-2log2e*y)) - 1
    float A[4], bias[4], Bk[3][4], Ck[3][4];
#pragma unroll
    for (int g = 0; g < 4; ++g) {
        const int col = g * 3 + u;
        const float sc = (g == 2) ? (-2.0f * LOG2E) : (-LOG2E);
        if (isL2) {
            A[g]    = 0.0f;
            bias[g] = __ldg(b2 + col) * sc;
#pragma unroll
            for (int k = 0; k < 3; ++k) {
                Bk[k][g] = __ldg(W2 + k * 12 + col) * sc;  // input = s1 broadcast
                Ck[k][g] = __ldg(U2 + k * 12 + col) * sc;  // state = h2 broadcast
            }
        } else {
            A[g]    = __ldg(W1 + col) * sc;
            bias[g] = __ldg(b1 + col) * sc;
#pragma unroll
            for (int k = 0; k < 3; ++k) {
                Bk[k][g] = __ldg(U1 + k * 12 + col) * sc;  // state = s1 broadcast
                Ck[k][g] = 0.0f;
            }
        }
    }

    const float* xrow = state + (size_t)b * (size_t)T;

    float cc = 0.0f;     // own-unit cell state
    float outv = 0.0f;   // own-unit hidden output (s1 for L1 lanes, h2 for L2 lanes)
    float S0 = 0.0f, S1 = 0.0f, S2 = 0.0f;   // broadcast s1(t-1)
    float H0 = 0.0f, H1 = 0.0f, H2 = 0.0f;   // broadcast h2(t-2)

#define STEP(xv)                                                           \
    do {                                                                   \
        float z0 = fmaf(A[0], (xv), bias[0]);                              \
        float z1 = fmaf(A[1], (xv), bias[1]);                              \
        float z2 = fmaf(A[2], (xv), bias[2]);                              \
        float z3 = fmaf(A[3], (xv), bias[3]);                              \
        z0 = fmaf(Bk[0][0], S0, z0); z1 = fmaf(Bk[0][1], S0, z1);          \
        z2 = fmaf(Bk[0][2], S0, z2); z3 = fmaf(Bk[0][3], S0, z3);          \
        z0 = fmaf(Bk[1][0], S1, z0); z1 = fmaf(Bk[1][1], S1, z1);          \
        z2 = fmaf(Bk[1][2], S1, z2); z3 = fmaf(Bk[1][3], S1, z3);          \
        z0 = fmaf(Bk[2][0], S2, z0); z1 = fmaf(Bk[2][1], S2, z1);          \
        z2 = fmaf(Bk[2][2], S2, z2); z3 = fmaf(Bk[2][3], S2, z3);          \
        z0 = fmaf(Ck[0][0], H0, z0); z1 = fmaf(Ck[0][1], H0, z1);          \
        z2 = fmaf(Ck[0][2], H0, z2); z3 = fmaf(Ck[0][3], H0, z3);          \
        z0 = fmaf(Ck[1][0], H1, z0); z1 = fmaf(Ck[1][1], H1, z1);          \
        z2 = fmaf(Ck[1][2], H1, z2); z3 = fmaf(Ck[1][3], H1, z3);          \
        z0 = fmaf(Ck[2][0], H2, z0); z1 = fmaf(Ck[2][1], H2, z1);          \
        z2 = fmaf(Ck[2][2], H2, z2); z3 = fmaf(Ck[2][3], H2, z3);          \
        const float d0 = 1.0f + fast_ex2(z0);                              \
        const float d1 = 1.0f + fast_ex2(z1);                              \
        const float d2 = 1.0f + fast_ex2(z2);                              \
        const float d3 = 1.0f + fast_ex2(z3);                              \
        const float si = fast_rcp(d0);                                     \
        const float sf = fast_rcp(d1);                                     \
        const float tg = fmaf(2.0f, fast_rcp(d2), -1.0f);                  \
        const float so = fast_rcp(d3);                                     \
        cc = fmaf(sf, cc, si * tg);                                        \
        const float tc = fmaf(2.0f,                                        \
            fast_rcp(1.0f + fast_ex2((-2.0f * LOG2E) * cc)), -1.0f);       \
        outv = so * tc;                                                    \
    } while (0)

#define BCAST()                                                            \
    do {                                                                   \
        S0 = __shfl_sync(FULLM, outv, 0, 8);                               \
        S1 = __shfl_sync(FULLM, outv, 1, 8);                               \
        S2 = __shfl_sync(FULLM, outv, 2, 8);                               \
        H0 = __shfl_sync(FULLM, outv, 4, 8);                               \
        H1 = __shfl_sync(FULLM, outv, 5, 8);                               \
        H2 = __shfl_sync(FULLM, outv, 6, 8);                               \
    } while (0)

    // ---- prologue: step 0. L1 lanes produce s1(0); L2 lanes produced
    // garbage (there is no h2(-1)) -> reset them before the first broadcast.
    STEP(__ldg(xrow + 0));
    if (isL2) { cc = 0.0f; outv = 0.0f; }
    BCAST();

    // ---- main loop: t = 1..T-1. L1 computes s1(t), L2 computes h2(t-1).
#pragma unroll 4
    for (int t = 1; t < T; ++t) {
        STEP(__ldg(xrow + t));
        BCAST();
    }

    // ---- epilogue: one more step so L2 lanes produce h2(T-1). x unused
    // by L2 lanes (A=0); L1 lanes compute garbage that is never read.
    STEP(0.0f);

    const float F0 = __shfl_sync(FULLM, outv, 4, 8);
    const float F1 = __shfl_sync(FULLM, outv, 5, 8);
    const float F2 = __shfl_sync(FULLM, outv, 6, 8);

    if (writer) {
        float r = __ldg(bd);
        r = fmaf(F0, __ldg(Wd + 0), r);
        r = fmaf(F1, __ldg(Wd + 1), r);
        r = fmaf(F2, __ldg(Wd + 2), r);
        out[b] = r;
    }

#undef STEP
#undef BCAST
}

extern "C" void kernel_launch(void* const* d_in, const int* in_sizes, int n_in,
                              void* d_out, int out_size)
{
    const float* state = (const float*)d_in[0];
    const float* W1 = (const float*)d_in[1];
    const float* U1 = (const float*)d_in[2];
    const float* b1 = (const float*)d_in[3];
    const float* W2 = (const float*)d_in[4];
    const float* U2 = (const float*)d_in[5];
    const float* b2 = (const float*)d_in[6];
    const float* Wd = (const float*)d_in[7];
    const float* bd = (const float*)d_in[8];
    float* out = (float*)d_out;

    const int B = out_size;            // output is [1, B]
    const int T = in_sizes[0] / B;     // state is [B, T]

    const long long total_threads = (long long)B * 8;   // 8 lanes per element
    const int threads = 256;                            // 8 warps = 2 per SMSP
    const int blocks = (int)((total_threads + threads - 1) / threads);
    lstm2_8lane_kernel<<<blocks, threads>>>(state, W1, U1, b1, W2, U2, b2, Wd, bd, out, B, T);
}